// round 15
// baseline (speedup 1.0000x reference)
#include <cuda_runtime.h>
#include <cstdint>

#define T_LEN 4096
#define IN_DIM 256
#define H_DIM 1024
#define G4H   4096
#define NCTA  128
#define UNITS 8     // hidden units per CTA (128 * 8 = 1024)
#define NREP  8     // publish-buffer replicas (slice de-amplification)
#define GEMM_BLKS 1024   // fused GEMM tile blocks
#define FC_BLKS   32     // fused FC blocks (128 timesteps each)

// ---------------- device scratch (static: no allocations allowed) ----------
__device__ float g_xz[(size_t)T_LEN * G4H];     // 64 MB: input projections
__device__ float g_hall[(size_t)T_LEN * H_DIM]; // 16 MB: h outputs of current layer
// Fused data+flag publish buffers (see R8/R13 analysis; replay-safe tags).
__device__ unsigned long long g_pub[2][NREP][H_DIM];
// Per-scan-CTA progress counters: value = layer*T_LEN + t + 1, released every
// 128 steps. Zeroed by gemm0 each replay (kernel boundary orders it).
__device__ unsigned g_prog[NCTA];

// ---------------- memory-order helpers --------------------------------------
__device__ __forceinline__ unsigned long long ld_relaxed64(const unsigned long long* p) {
    unsigned long long v;
    asm volatile("ld.relaxed.gpu.global.b64 %0, [%1];" : "=l"(v) : "l"(p) : "memory");
    return v;
}
__device__ __forceinline__ void st_relaxed64(unsigned long long* p, unsigned long long v) {
    asm volatile("st.relaxed.gpu.global.b64 [%0], %1;" :: "l"(p), "l"(v) : "memory");
}
__device__ __forceinline__ unsigned ld_acquire32(const unsigned* p) {
    unsigned v;
    asm volatile("ld.acquire.gpu.global.u32 %0, [%1];" : "=r"(v) : "l"(p) : "memory");
    return v;
}
__device__ __forceinline__ void st_release32(unsigned* p, unsigned v) {
    asm volatile("st.release.gpu.global.u32 [%0], %1;" :: "l"(p), "r"(v) : "memory");
}

// ---------------- packed f32x2 FMA helpers ----------------------------------
union F2u { float2 f; unsigned long long u; };

__device__ __forceinline__ void fma2(unsigned long long& d,
                                     unsigned long long a,
                                     unsigned long long b) {
    asm volatile("fma.rn.f32x2 %0, %1, %2, %0;" : "+l"(d) : "l"(a), "l"(b));
}
__device__ __forceinline__ unsigned long long pack2(float lo, float hi) {
    unsigned long long r;
    asm("mov.b64 %0, {%1, %2};" : "=l"(r) : "f"(lo), "f"(hi));
    return r;
}

// ---------------- fast, overflow-safe activations ---------------------------
__device__ __forceinline__ float fast_sigmoid(float x) {
    return __fdividef(1.f, 1.f + __expf(-x));
}
__device__ __forceinline__ float fast_tanh(float x) {
    float a = fabsf(x);
    float e = __expf(-2.f * a);
    float t = (1.f - e) * __fdividef(1.f, 1.f + e);
    return copysignf(t, x);
}

// ---------------- standalone GEMM (layer 0 input projection) ----------------
// Also zeroes g_prog for the fused pipeline (kernel boundary orders it).
template<int K>
__global__ __launch_bounds__(256)
void gemm_xz(const float* __restrict__ A,
             const float* __restrict__ W,
             const float* __restrict__ bias) {
    __shared__ float As[16][132];
    __shared__ float Bs[16][132];

    const int tid  = threadIdx.x;
    if (blockIdx.x == 0 && blockIdx.y == 0 && tid < NCTA) g_prog[tid] = 0;

    const int row0 = blockIdx.y * 128;
    const int col0 = blockIdx.x * 128;
    const int ty   = tid >> 4;
    const int tx   = tid & 15;
    const int lr   = tid >> 2;
    const int lc   = tid & 3;

    unsigned long long acc2[8][4];
#pragma unroll
    for (int i = 0; i < 8; i++)
#pragma unroll
        for (int j = 0; j < 4; j++) acc2[i][j] = pack2(0.f, 0.f);

    const float* pA0 = A + (size_t)(row0 + lr) * K + lc * 4;
    const float* pA1 = A + (size_t)(row0 + lr + 64) * K + lc * 4;
    const float* pB0 = W + (size_t)(col0 + lr) * K + lc * 4;
    const float* pB1 = W + (size_t)(col0 + lr + 64) * K + lc * 4;

    float4 fa0 = *(const float4*)(pA0);
    float4 fa1 = *(const float4*)(pA1);
    float4 fb0 = *(const float4*)(pB0);
    float4 fb1 = *(const float4*)(pB1);

    for (int k0 = 0; k0 < K; k0 += 16) {
        __syncthreads();
        As[lc * 4 + 0][lr] = fa0.x; As[lc * 4 + 1][lr] = fa0.y;
        As[lc * 4 + 2][lr] = fa0.z; As[lc * 4 + 3][lr] = fa0.w;
        As[lc * 4 + 0][lr + 64] = fa1.x; As[lc * 4 + 1][lr + 64] = fa1.y;
        As[lc * 4 + 2][lr + 64] = fa1.z; As[lc * 4 + 3][lr + 64] = fa1.w;
        Bs[lc * 4 + 0][lr] = fb0.x; Bs[lc * 4 + 1][lr] = fb0.y;
        Bs[lc * 4 + 2][lr] = fb0.z; Bs[lc * 4 + 3][lr] = fb0.w;
        Bs[lc * 4 + 0][lr + 64] = fb1.x; Bs[lc * 4 + 1][lr + 64] = fb1.y;
        Bs[lc * 4 + 2][lr + 64] = fb1.z; Bs[lc * 4 + 3][lr + 64] = fb1.w;
        __syncthreads();

        if (k0 + 16 < K) {
            fa0 = *(const float4*)(pA0 + k0 + 16);
            fa1 = *(const float4*)(pA1 + k0 + 16);
            fb0 = *(const float4*)(pB0 + k0 + 16);
            fb1 = *(const float4*)(pB1 + k0 + 16);
        }

#pragma unroll
        for (int k = 0; k < 16; k++) {
            float4 a0 = *(const float4*)&As[k][ty * 8];
            float4 a1 = *(const float4*)&As[k][ty * 8 + 4];
            float4 b0 = *(const float4*)&Bs[k][tx * 8];
            float4 b1 = *(const float4*)&Bs[k][tx * 8 + 4];
            unsigned long long bp[4];
            bp[0] = pack2(b0.x, b0.y); bp[1] = pack2(b0.z, b0.w);
            bp[2] = pack2(b1.x, b1.y); bp[3] = pack2(b1.z, b1.w);
            float a[8] = {a0.x, a0.y, a0.z, a0.w, a1.x, a1.y, a1.z, a1.w};
#pragma unroll
            for (int i = 0; i < 8; i++) {
                unsigned long long ap = pack2(a[i], a[i]);
#pragma unroll
                for (int j = 0; j < 4; j++) fma2(acc2[i][j], ap, bp[j]);
            }
        }
    }

    float bj[8];
#pragma unroll
    for (int j = 0; j < 8; j++) bj[j] = bias[col0 + tx * 8 + j];
#pragma unroll
    for (int i = 0; i < 8; i++) {
        int r = row0 + ty * 8 + i;
        float* orow = g_xz + (size_t)r * G4H + col0 + tx * 8;
#pragma unroll
        for (int j = 0; j < 4; j++) {
            F2u v; v.u = acc2[i][j];
            orow[2 * j + 0] = v.f.x + bj[2 * j + 0];
            orow[2 * j + 1] = v.f.y + bj[2 * j + 1];
        }
    }
}

// ---------------- FUSED: scan(layer) [blocks 0..127] + gemm(layer+1) or FC --
// Scan path = R13 verbatim + progress release every 128 steps.
// Extra blocks (blockIdx >= NCTA):
//   Wnext != nullptr -> gemm(layer+1) tile, gated on g_prog (128-row chunks)
//   Wnext == nullptr -> FC over 128 timesteps, gated on g_prog (layer 3)
// All g_hall reads in extra blocks use __ldcg (L1 not coherent with the
// concurrent scan writes).
__global__ __launch_bounds__(256, 1)
void fused_scan_gemm(const float* __restrict__ Whh, int layer,
                     const float* __restrict__ Wnext,
                     const float* __restrict__ bnext,
                     const float* __restrict__ fcW,
                     const float* __restrict__ fcb,
                     float* __restrict__ out) {
    const int tid = threadIdx.x;

    if (blockIdx.x >= NCTA) {
        if (Wnext != nullptr) {
            // ================= GEMM branch (layer+1 input projection) ======
            __shared__ float As[16][132];
            __shared__ float Bs[16][132];

            const int g    = blockIdx.x - NCTA;
            const int row0 = (g >> 5) * 128;
            const int col0 = (g & 31) * 128;

            {
                const unsigned target = (unsigned)(layer * T_LEN + row0 + 128);
                if (tid < NCTA) {
                    while (ld_acquire32(&g_prog[tid]) < target) __nanosleep(256);
                }
                __syncthreads();
            }

            const int ty = tid >> 4, tx = tid & 15;
            const int lr = tid >> 2, lc = tid & 3;

            unsigned long long acc2[8][4];
#pragma unroll
            for (int i = 0; i < 8; i++)
#pragma unroll
                for (int j = 0; j < 4; j++) acc2[i][j] = pack2(0.f, 0.f);

            const float* pA0 = g_hall + (size_t)(row0 + lr) * H_DIM + lc * 4;
            const float* pA1 = g_hall + (size_t)(row0 + lr + 64) * H_DIM + lc * 4;
            const float* pB0 = Wnext + (size_t)(col0 + lr) * H_DIM + lc * 4;
            const float* pB1 = Wnext + (size_t)(col0 + lr + 64) * H_DIM + lc * 4;

            float4 fa0 = __ldcg((const float4*)(pA0));
            float4 fa1 = __ldcg((const float4*)(pA1));
            float4 fb0 = *(const float4*)(pB0);
            float4 fb1 = *(const float4*)(pB1);

            for (int k0 = 0; k0 < H_DIM; k0 += 16) {
                __syncthreads();
                As[lc * 4 + 0][lr] = fa0.x; As[lc * 4 + 1][lr] = fa0.y;
                As[lc * 4 + 2][lr] = fa0.z; As[lc * 4 + 3][lr] = fa0.w;
                As[lc * 4 + 0][lr + 64] = fa1.x; As[lc * 4 + 1][lr + 64] = fa1.y;
                As[lc * 4 + 2][lr + 64] = fa1.z; As[lc * 4 + 3][lr + 64] = fa1.w;
                Bs[lc * 4 + 0][lr] = fb0.x; Bs[lc * 4 + 1][lr] = fb0.y;
                Bs[lc * 4 + 2][lr] = fb0.z; Bs[lc * 4 + 3][lr] = fb0.w;
                Bs[lc * 4 + 0][lr + 64] = fb1.x; Bs[lc * 4 + 1][lr + 64] = fb1.y;
                Bs[lc * 4 + 2][lr + 64] = fb1.z; Bs[lc * 4 + 3][lr + 64] = fb1.w;
                __syncthreads();

                if (k0 + 16 < H_DIM) {
                    fa0 = __ldcg((const float4*)(pA0 + k0 + 16));
                    fa1 = __ldcg((const float4*)(pA1 + k0 + 16));
                    fb0 = *(const float4*)(pB0 + k0 + 16);
                    fb1 = *(const float4*)(pB1 + k0 + 16);
                }

#pragma unroll
                for (int k = 0; k < 16; k++) {
                    float4 a0 = *(const float4*)&As[k][ty * 8];
                    float4 a1 = *(const float4*)&As[k][ty * 8 + 4];
                    float4 b0 = *(const float4*)&Bs[k][tx * 8];
                    float4 b1 = *(const float4*)&Bs[k][tx * 8 + 4];
                    unsigned long long bp[4];
                    bp[0] = pack2(b0.x, b0.y); bp[1] = pack2(b0.z, b0.w);
                    bp[2] = pack2(b1.x, b1.y); bp[3] = pack2(b1.z, b1.w);
                    float a[8] = {a0.x, a0.y, a0.z, a0.w, a1.x, a1.y, a1.z, a1.w};
#pragma unroll
                    for (int i = 0; i < 8; i++) {
                        unsigned long long ap = pack2(a[i], a[i]);
#pragma unroll
                        for (int j = 0; j < 4; j++) fma2(acc2[i][j], ap, bp[j]);
                    }
                }
            }

            float bj[8];
#pragma unroll
            for (int j = 0; j < 8; j++) bj[j] = bnext[col0 + tx * 8 + j];
#pragma unroll
            for (int i = 0; i < 8; i++) {
                int r = row0 + ty * 8 + i;
                float* orow = g_xz + (size_t)r * G4H + col0 + tx * 8;
#pragma unroll
                for (int j = 0; j < 4; j++) {
                    F2u v; v.u = acc2[i][j];
                    orow[2 * j + 0] = v.f.x + bj[2 * j + 0];
                    orow[2 * j + 1] = v.f.y + bj[2 * j + 1];
                }
            }
        } else {
            // ================= FC branch (final projection, layer 3) =======
            const int c  = blockIdx.x - NCTA;     // 0..31, timesteps [128c,128c+128)
            const int wd = tid >> 5;
            const int ln = tid & 31;

            {
                const unsigned target = (unsigned)(layer * T_LEN + 128 * (c + 1));
                if (tid < NCTA) {
                    while (ld_acquire32(&g_prog[tid]) < target) __nanosleep(256);
                }
                __syncthreads();
            }

            // warp-task loop: 128 timesteps x 10 outputs = 1280 tasks, 8 warps
            for (int task = wd; task < 128 * 10; task += 8) {
                int t = 128 * c + task / 10;
                int o = task % 10;
                const float4* h = (const float4*)(g_hall + (size_t)t * H_DIM);
                const float4* w = (const float4*)(fcW + (size_t)o * H_DIM);
                float s = 0.f;
#pragma unroll
                for (int cc = 0; cc < 8; cc++) {
                    float4 hv = __ldcg(h + cc * 32 + ln);
                    float4 wv = w[cc * 32 + ln];
                    s += hv.x * wv.x + hv.y * wv.y + hv.z * wv.z + hv.w * wv.w;
                }
#pragma unroll
                for (int off = 16; off; off >>= 1)
                    s += __shfl_xor_sync(0xffffffffu, s, off);
                if (ln == 0) out[t * 10 + o] = s + fcb[o];
            }
        }
        return;
    }

    // ==================== SCAN branch (R13 verbatim + progress) =============
    __shared__ float sh_h[H_DIM];
    __shared__ float sh_z[32];

    const int bid   = blockIdx.x;
    const int wid   = tid >> 5;
    const int lane  = tid & 31;
    const int ubase = bid * UNITS;
    const int rep   = bid & (NREP - 1);

    float4 wreg[4][8];
#pragma unroll
    for (int j = 0; j < 4; j++) {
        int s    = wid * 4 + j;
        int gate = s >> 3;
        int unit = s & 7;
        const float4* wr =
            (const float4*)(Whh + ((size_t)gate * H_DIM + ubase + unit) * H_DIM);
#pragma unroll
        for (int c = 0; c < 8; c++) wreg[j][c] = wr[c * 32 + lane];
    }

    const unsigned tagbase = (unsigned)layer * (unsigned)(T_LEN + 1);
    float c_state = 0.f;

    if (tid < UNITS) {
        unsigned long long pk = (unsigned long long)tagbase << 32;
#pragma unroll
        for (int r = 0; r < NREP; r++)
            st_relaxed64(&g_pub[1][r][ubase + tid], pk);
    }

    for (int t = 0; t < T_LEN; t++) {
        float xzi = 0.f, xzf = 0.f, xzg = 0.f, xzo = 0.f;
        if (tid < UNITS) {
            const float* xz = g_xz + (size_t)t * G4H + ubase + tid;
            xzi = __ldg(xz);
            xzf = __ldg(xz + H_DIM);
            xzg = __ldg(xz + 2 * H_DIM);
            xzo = __ldg(xz + 3 * H_DIM);
        }

        {
            unsigned long long* buf = g_pub[(t + 1) & 1][rep];
            const unsigned exp_tag  = tagbase + (unsigned)t;
            unsigned long long pr0, pr1, pr2, pr3;
            int tries = 0;
            for (;;) {
                pr0 = ld_relaxed64(buf + 4 * tid + 0);
                pr1 = ld_relaxed64(buf + 4 * tid + 1);
                pr2 = ld_relaxed64(buf + 4 * tid + 2);
                pr3 = ld_relaxed64(buf + 4 * tid + 3);
                bool ok = ((unsigned)(pr0 >> 32) == exp_tag) &
                          ((unsigned)(pr1 >> 32) == exp_tag) &
                          ((unsigned)(pr2 >> 32) == exp_tag) &
                          ((unsigned)(pr3 >> 32) == exp_tag);
                if (ok) break;
                if (++tries > 2) __nanosleep(40);
            }
            ((float4*)sh_h)[tid] =
                make_float4(__uint_as_float((unsigned)pr0),
                            __uint_as_float((unsigned)pr1),
                            __uint_as_float((unsigned)pr2),
                            __uint_as_float((unsigned)pr3));
        }
        __syncthreads();                                   // (B)

        unsigned long long acc[4];
        {
            F2u z; z.f = make_float2(0.f, 0.f);
            acc[0] = acc[1] = acc[2] = acc[3] = z.u;
        }
#pragma unroll
        for (int c = 0; c < 8; c++) {
            float4 hv = ((const float4*)sh_h)[c * 32 + lane];
            F2u hlo, hhi;
            hlo.f = make_float2(hv.x, hv.y);
            hhi.f = make_float2(hv.z, hv.w);
#pragma unroll
            for (int j = 0; j < 4; j++) {
                F2u wlo, whi;
                wlo.f = make_float2(wreg[j][c].x, wreg[j][c].y);
                whi.f = make_float2(wreg[j][c].z, wreg[j][c].w);
                fma2(acc[j], wlo.u, hlo.u);
                fma2(acc[j], whi.u, hhi.u);
            }
        }

        float s0, s1, s2, s3;
        {
            F2u a0, a1, a2, a3;
            a0.u = acc[0]; a1.u = acc[1]; a2.u = acc[2]; a3.u = acc[3];
            s0 = a0.f.x + a0.f.y;
            s1 = a1.f.x + a1.f.y;
            s2 = a2.f.x + a2.f.y;
            s3 = a3.f.x + a3.f.y;
#pragma unroll
            for (int off = 16; off; off >>= 1) {
                s0 += __shfl_xor_sync(0xffffffffu, s0, off);
                s1 += __shfl_xor_sync(0xffffffffu, s1, off);
                s2 += __shfl_xor_sync(0xffffffffu, s2, off);
                s3 += __shfl_xor_sync(0xffffffffu, s3, off);
            }
        }
        if (lane == 0) {
            sh_z[wid * 4 + 0] = s0;
            sh_z[wid * 4 + 1] = s1;
            sh_z[wid * 4 + 2] = s2;
            sh_z[wid * 4 + 3] = s3;
        }
        __syncthreads();                                   // (C)

        if (tid < UNITS) {
            float zi = sh_z[tid]      + xzi;
            float zf = sh_z[8 + tid]  + xzf;
            float zg = sh_z[16 + tid] + xzg;
            float zo = sh_z[24 + tid] + xzo;
            float ig = fast_sigmoid(zi);
            float fg = fast_sigmoid(zf);
            float gg = fast_tanh(zg);
            float og = fast_sigmoid(zo);
            c_state  = fg * c_state + ig * gg;
            float h  = og * fast_tanh(c_state);
            unsigned long long pk =
                ((unsigned long long)(tagbase + (unsigned)t + 1u) << 32) |
                (unsigned long long)__float_as_uint(h);
            unsigned long long* dst = &g_pub[t & 1][0][ubase + tid];
#pragma unroll
            for (int r = 0; r < NREP; r++)
                st_relaxed64(dst + (size_t)r * H_DIM, pk);
            g_hall[(size_t)t * H_DIM + ubase + tid] = h;

            if ((t & 127) == 127) {
                __syncwarp(0x000000ffu);
                if (tid == 0)
                    st_release32(&g_prog[bid],
                                 (unsigned)(layer * T_LEN) + (unsigned)t + 1u);
            }
        }
    }
}

// ---------------- launch ----------------------------------------------------
extern "C" void kernel_launch(void* const* d_in, const int* in_sizes, int n_in,
                              void* d_out, int out_size) {
    const float* x     = (const float*)d_in[0];
    const float* Wih0  = (const float*)d_in[1];
    const float* Whh0  = (const float*)d_in[2];
    const float* b0    = (const float*)d_in[3];
    const float* WihR  = (const float*)d_in[4];
    const float* WhhR  = (const float*)d_in[5];
    const float* bR    = (const float*)d_in[6];
    const float* fcW   = (const float*)d_in[7];
    const float* fcb   = (const float*)d_in[8];
    float*       out   = (float*)d_out;

    const size_t wstride = (size_t)G4H * H_DIM;

    // layer-0 input projection (also zeroes g_prog for this replay)
    dim3 ggrid(G4H / 128, T_LEN / 128);
    gemm_xz<IN_DIM><<<ggrid, 256>>>(x, Wih0, b0);

    // K_l = scan(l) + gemm(l+1), l = 0..2
    fused_scan_gemm<<<NCTA + GEMM_BLKS, 256>>>(Whh0, 0, WihR, bR,
                                               nullptr, nullptr, nullptr);
    fused_scan_gemm<<<NCTA + GEMM_BLKS, 256>>>(WhhR, 1, WihR + wstride, bR + G4H,
                                               nullptr, nullptr, nullptr);
    fused_scan_gemm<<<NCTA + GEMM_BLKS, 256>>>(WhhR + wstride, 2,
                                               WihR + 2 * wstride, bR + 2 * G4H,
                                               nullptr, nullptr, nullptr);
    // K_3 = scan(3) + fused FC
    fused_scan_gemm<<<NCTA + FC_BLKS, 256>>>(WhhR + 2 * wstride, 3,
                                             nullptr, nullptr, fcW, fcb, out);
}